// round 8
// baseline (speedup 1.0000x reference)
#include <cuda_runtime.h>
#include <cuda_bf16.h>

// Distance_74406013436418: trilinear SDF interpolation + finite-difference
// normals + hinge loss.
//
// Output (float32): [dss B*N | nss B*N*3 | loss 1]
//
// R7: single-node graph, R3 compute body. Loss finalization via a ticket
// counter using one atom.acq_rel.gpu.add (NO full __threadfence — the
// per-block MEMBAR.GPU drain cost ~2us in R6). Counter grows monotonically;
// winner = (ticket % gridDim == gridDim-1), exactly one per replay, and
// 2^32 % 2048 == 0 so wraparound preserves the modulus. Streaming-store
// hints on outputs (zero reuse).

#define EPS 1e-5f
#define TPB 256

// per-block loss partials (fully overwritten each launch -> deterministic)
__device__ float g_partials[8192];
// monotone ticket counter (see header comment for replay-safety argument)
__device__ unsigned int g_count = 0;

__global__ __launch_bounds__(TPB)
void sdf_trilinear_kernel(const float* __restrict__ pss,
                          const float* __restrict__ grid,
                          const float* __restrict__ first,
                          const float* __restrict__ coef,
                          const float* __restrict__ maxl,
                          float* __restrict__ dss,
                          float* __restrict__ nss,
                          float* __restrict__ loss,
                          int N, int D, int total)
{
    int t = blockIdx.x * TPB + threadIdx.x;

    float my_loss = 0.0f;

    if (t < total) {
        int b = t / N;
        int n = t - b * N;

        // point coords (coalesced: stride-1 in n)
        float px = pss[((size_t)b * 3 + 0) * N + n];
        float py = pss[((size_t)b * 3 + 1) * N + n];
        float pz = pss[((size_t)b * 3 + 2) * N + n];

        float f0x = first[b * 3 + 0], f0y = first[b * 3 + 1], f0z = first[b * 3 + 2];
        float cx  = coef[b * 3 + 0],  cy  = coef[b * 3 + 1],  cz  = coef[b * 3 + 2];
        float mx  = maxl[b * 3 + 0],  my  = maxl[b * 3 + 1],  mz  = maxl[b * 3 + 2];

        float fx_full = fmaxf(fminf((px - f0x) * cx, mx), 0.0f);
        float fy_full = fmaxf(fminf((py - f0y) * cy, my), 0.0f);
        float fz_full = fmaxf(fminf((pz - f0z) * cz, mz), 0.0f);

        float bx = floorf(fx_full);
        float by = floorf(fy_full);
        float bz = floorf(fz_full);
        float fx = fx_full - bx;
        float fy = fy_full - by;
        float fz = fz_full - bz;

        int ix = (int)bx, iy = (int)by, iz = (int)bz;
        const int DD = D * D;

        const float* g = grid + (size_t)b * D * DD
                              + (size_t)ix * DD
                              + (size_t)iy * D
                              + (size_t)iz;

        // 8 gathers issued back-to-back (all independent)
        float c000 = __ldg(g);
        float c001 = __ldg(g + 1);
        float c010 = __ldg(g + D);
        float c011 = __ldg(g + D + 1);
        float c100 = __ldg(g + DD);
        float c101 = __ldg(g + DD + 1);
        float c110 = __ldg(g + DD + D);
        float c111 = __ldg(g + DD + D + 1);

        float wx0 = 1.0f - fx, wx1 = fx;
        float wy0 = 1.0f - fy, wy1 = fy;
        float wz0 = 1.0f - fz, wz1 = fz;

        // trilinear value (lerp chain: z, then y, then x)
        float a00 = fmaf(fz, c001 - c000, c000);
        float a01 = fmaf(fz, c011 - c010, c010);
        float a10 = fmaf(fz, c101 - c100, c100);
        float a11 = fmaf(fz, c111 - c110, c110);
        float b0  = fmaf(fy, a01 - a00, a00);
        float b1  = fmaf(fy, a11 - a10, a10);
        float d   = fmaf(fx, b1 - b0, b0);

        // finite-difference normals
        float nz = ((c001-c000) * wy0 + (c011-c010) * wy1) * wx0
                 + ((c101-c100) * wy0 + (c111-c110) * wy1) * wx1;
        float ny = ((c010-c000) * wz0 + (c011-c001) * wz1) * wx0
                 + ((c110-c100) * wz0 + (c111-c101) * wz1) * wx1;
        float nx = ((c100-c000) * wz0 + (c101-c001) * wz1) * wy0
                 + ((c110-c010) * wz0 + (c111-c011) * wz1) * wy1;

        float norm = sqrtf(nx * nx + ny * ny + nz * nz);
        float inv  = 1.0f / fmaxf(norm, EPS);

        // streaming stores: outputs have zero reuse, don't pollute L2
        __stcs(dss + t, d);
        __stcs(nss + 3 * (size_t)t + 0, nx * inv);
        __stcs(nss + 3 * (size_t)t + 1, ny * inv);
        __stcs(nss + 3 * (size_t)t + 2, nz * inv);

        my_loss = -fminf(d, 0.0f);
    }

    // block reduction of loss
    __shared__ float warp_sums[TPB / 32];
    __shared__ bool  is_last;
    int lane = threadIdx.x & 31;
    int warp = threadIdx.x >> 5;

    #pragma unroll
    for (int off = 16; off > 0; off >>= 1)
        my_loss += __shfl_down_sync(0xFFFFFFFFu, my_loss, off);
    if (lane == 0) warp_sums[warp] = my_loss;
    __syncthreads();

    if (warp == 0) {
        float s = (lane < (TPB >> 5)) ? warp_sums[lane] : 0.0f;
        #pragma unroll
        for (int off = 4; off > 0; off >>= 1)
            s += __shfl_down_sync(0xFFFFFFFFu, s, off);
        if (lane == 0) {
            // plain store of this block's partial, then a RELEASE atomic on the
            // ticket. No MEMBAR.GPU: the release orders the partial store.
            g_partials[blockIdx.x] = s;
            unsigned int ticket;
            asm volatile("atom.acq_rel.gpu.global.add.u32 %0, [%1], %2;"
                         : "=r"(ticket) : "l"(&g_count), "r"(1u) : "memory");
            is_last = (ticket % gridDim.x) == (gridDim.x - 1);
        }
    }
    __syncthreads();

    // last block to finish sums all partials and writes the scalar loss
    if (is_last) {
        // acquire for the whole block (winner's lane0 atomic had acquire, but
        // other threads in this block need the ordering too; one block only —
        // negligible cost)
        __threadfence();
        float s = 0.0f;
        for (int i = threadIdx.x; i < (int)gridDim.x; i += TPB)
            s += __ldcg(&g_partials[i]);   // L1-bypass: read L2-visible values

        #pragma unroll
        for (int off = 16; off > 0; off >>= 1)
            s += __shfl_down_sync(0xFFFFFFFFu, s, off);
        if (lane == 0) warp_sums[warp] = s;
        __syncthreads();
        if (warp == 0) {
            float v = (lane < (TPB >> 5)) ? warp_sums[lane] : 0.0f;
            #pragma unroll
            for (int off = 4; off > 0; off >>= 1)
                v += __shfl_down_sync(0xFFFFFFFFu, v, off);
            if (lane == 0) *loss = v;
        }
    }
}

extern "C" void kernel_launch(void* const* d_in, const int* in_sizes, int n_in,
                              void* d_out, int out_size)
{
    const float* pss   = (const float*)d_in[0];
    const float* grid  = (const float*)d_in[1];
    const float* first = (const float*)d_in[2];
    const float* coef  = (const float*)d_in[3];
    const float* maxl  = (const float*)d_in[4];

    int B = in_sizes[2] / 3;
    int N = in_sizes[0] / (3 * B);
    long per_b = (long)in_sizes[1] / B;
    int D = 1;
    while ((long)(D + 1) * (D + 1) * (D + 1) <= per_b) D++;

    int total = B * N;

    float* dss  = (float*)d_out;
    float* nss  = dss + (size_t)total;
    float* loss = dss + (size_t)4 * total;

    int blocks = (total + TPB - 1) / TPB;
    sdf_trilinear_kernel<<<blocks, TPB>>>(pss, grid, first, coef, maxl,
                                          dss, nss, loss, N, D, total);
}

// round 9
// speedup vs baseline: 1.0597x; 1.0597x over previous
#include <cuda_runtime.h>
#include <cuda_bf16.h>

// Distance_74406013436418: trilinear SDF interpolation + finite-difference
// normals + hinge loss.
//
// Output (float32): [dss B*N | nss B*N*3 | loss 1]
//
// R9: R3 body verbatim (plain stores, plain atomicAdd loss, memset node for
// the loss slot) wrapped in a persistent grid-stride loop at exactly one
// wave (148 SMs x occ 8 = 1184 blocks). Self-balances the random-gather
// completion spread and removes the 73%-full second wave of R3.
// Ticket machinery and __stcs from R6/R7 are reverted (measured regressions).

#define EPS 1e-5f
#define TPB 256
#define NBLOCKS 1184   // 148 SMs * 8 blocks/SM (31 regs, 256 thr -> occ 8)

__global__ __launch_bounds__(TPB)
void sdf_trilinear_kernel(const float* __restrict__ pss,
                          const float* __restrict__ grid,
                          const float* __restrict__ first,
                          const float* __restrict__ coef,
                          const float* __restrict__ maxl,
                          float* __restrict__ dss,
                          float* __restrict__ nss,
                          float* __restrict__ loss,
                          int N, int D, int total)
{
    const int DD = D * D;
    const int stride = gridDim.x * TPB;

    float my_loss = 0.0f;

    for (int t = blockIdx.x * TPB + threadIdx.x; t < total; t += stride) {
        int b = t / N;
        int n = t - b * N;

        // point coords (coalesced: stride-1 in n)
        float px = pss[((size_t)b * 3 + 0) * N + n];
        float py = pss[((size_t)b * 3 + 1) * N + n];
        float pz = pss[((size_t)b * 3 + 2) * N + n];

        float f0x = first[b * 3 + 0], f0y = first[b * 3 + 1], f0z = first[b * 3 + 2];
        float cx  = coef[b * 3 + 0],  cy  = coef[b * 3 + 1],  cz  = coef[b * 3 + 2];
        float mx  = maxl[b * 3 + 0],  my  = maxl[b * 3 + 1],  mz  = maxl[b * 3 + 2];

        float fx_full = fmaxf(fminf((px - f0x) * cx, mx), 0.0f);
        float fy_full = fmaxf(fminf((py - f0y) * cy, my), 0.0f);
        float fz_full = fmaxf(fminf((pz - f0z) * cz, mz), 0.0f);

        float bx = floorf(fx_full);
        float by = floorf(fy_full);
        float bz = floorf(fz_full);
        float fx = fx_full - bx;
        float fy = fy_full - by;
        float fz = fz_full - bz;

        int ix = (int)bx, iy = (int)by, iz = (int)bz;

        const float* g = grid + (size_t)b * D * DD
                              + (size_t)ix * DD
                              + (size_t)iy * D
                              + (size_t)iz;

        // 8 gathers issued back-to-back (all independent)
        float c000 = __ldg(g);
        float c001 = __ldg(g + 1);
        float c010 = __ldg(g + D);
        float c011 = __ldg(g + D + 1);
        float c100 = __ldg(g + DD);
        float c101 = __ldg(g + DD + 1);
        float c110 = __ldg(g + DD + D);
        float c111 = __ldg(g + DD + D + 1);

        float wx0 = 1.0f - fx, wx1 = fx;
        float wy0 = 1.0f - fy, wy1 = fy;
        float wz0 = 1.0f - fz, wz1 = fz;

        // trilinear value (lerp chain: z, then y, then x)
        float a00 = fmaf(fz, c001 - c000, c000);
        float a01 = fmaf(fz, c011 - c010, c010);
        float a10 = fmaf(fz, c101 - c100, c100);
        float a11 = fmaf(fz, c111 - c110, c110);
        float b0  = fmaf(fy, a01 - a00, a00);
        float b1  = fmaf(fy, a11 - a10, a10);
        float d   = fmaf(fx, b1 - b0, b0);

        // finite-difference normals
        float nz = ((c001-c000) * wy0 + (c011-c010) * wy1) * wx0
                 + ((c101-c100) * wy0 + (c111-c110) * wy1) * wx1;
        float ny = ((c010-c000) * wz0 + (c011-c001) * wz1) * wx0
                 + ((c110-c100) * wz0 + (c111-c101) * wz1) * wx1;
        float nx = ((c100-c000) * wz0 + (c101-c001) * wz1) * wy0
                 + ((c110-c010) * wz0 + (c111-c011) * wz1) * wy1;

        float norm = sqrtf(nx * nx + ny * ny + nz * nz);
        float inv  = 1.0f / fmaxf(norm, EPS);

        dss[t] = d;
        nss[3 * (size_t)t + 0] = nx * inv;
        nss[3 * (size_t)t + 1] = ny * inv;
        nss[3 * (size_t)t + 2] = nz * inv;

        my_loss += -fminf(d, 0.0f);
    }

    // block reduction of loss, one atomic per block
    __shared__ float warp_sums[TPB / 32];
    int lane = threadIdx.x & 31;
    int warp = threadIdx.x >> 5;

    #pragma unroll
    for (int off = 16; off > 0; off >>= 1)
        my_loss += __shfl_down_sync(0xFFFFFFFFu, my_loss, off);
    if (lane == 0) warp_sums[warp] = my_loss;
    __syncthreads();

    if (warp == 0) {
        float s = (lane < (TPB >> 5)) ? warp_sums[lane] : 0.0f;
        #pragma unroll
        for (int off = 4; off > 0; off >>= 1)
            s += __shfl_down_sync(0xFFFFFFFFu, s, off);
        if (lane == 0)
            atomicAdd(loss, s);
    }
}

extern "C" void kernel_launch(void* const* d_in, const int* in_sizes, int n_in,
                              void* d_out, int out_size)
{
    const float* pss   = (const float*)d_in[0];
    const float* grid  = (const float*)d_in[1];
    const float* first = (const float*)d_in[2];
    const float* coef  = (const float*)d_in[3];
    const float* maxl  = (const float*)d_in[4];

    int B = in_sizes[2] / 3;
    int N = in_sizes[0] / (3 * B);
    long per_b = (long)in_sizes[1] / B;
    int D = 1;
    while ((long)(D + 1) * (D + 1) * (D + 1) <= per_b) D++;

    int total = B * N;

    float* dss  = (float*)d_out;
    float* nss  = dss + (size_t)total;
    float* loss = dss + (size_t)4 * total;

    // zero the loss accumulator (d_out is poisoned) — capturable async memset
    cudaMemsetAsync(loss, 0, sizeof(float));

    int blocks = NBLOCKS;
    int max_needed = (total + TPB - 1) / TPB;
    if (blocks > max_needed) blocks = max_needed;

    sdf_trilinear_kernel<<<blocks, TPB>>>(pss, grid, first, coef, maxl,
                                          dss, nss, loss, N, D, total);
}

// round 10
// speedup vs baseline: 1.1226x; 1.0593x over previous
#include <cuda_runtime.h>
#include <cuda_bf16.h>

// Distance_74406013436418: trilinear SDF interpolation + finite-difference
// normals + hinge loss.
//
// Output (float32): [dss B*N | nss B*N*3 | loss 1]
//
// R10: R3 structure restored exactly (measured-best: simple grid, plain
// stores, one atomicAdd/block, memset node for loss). Micro-trims only:
//  - 2D grid: blockIdx.y = batch  -> no t/N division, uniform batch scalars
//  - rsqrtf with min-clamp: 1/max(sqrt(s),eps) == min(rsqrt(s), 1/eps)
// Ticket reduction / __stcs / persistent loop all reverted (measured losses).

#define EPS 1e-5f
#define TPB 256

__global__ __launch_bounds__(TPB)
void sdf_trilinear_kernel(const float* __restrict__ pss,
                          const float* __restrict__ grid,
                          const float* __restrict__ first,
                          const float* __restrict__ coef,
                          const float* __restrict__ maxl,
                          float* __restrict__ dss,
                          float* __restrict__ nss,
                          float* __restrict__ loss,
                          int N, int D)
{
    const int b = blockIdx.y;                       // batch index (uniform)
    const int n = blockIdx.x * TPB + threadIdx.x;   // point index within batch
    const int DD = D * D;

    float my_loss = 0.0f;

    if (n < N) {
        const int t = b * N + n;                    // global output index

        // point coords (coalesced: stride-1 in n)
        float px = pss[((size_t)b * 3 + 0) * N + n];
        float py = pss[((size_t)b * 3 + 1) * N + n];
        float pz = pss[((size_t)b * 3 + 2) * N + n];

        // per-batch scalars: b is block-uniform -> single broadcast loads
        float f0x = first[b * 3 + 0], f0y = first[b * 3 + 1], f0z = first[b * 3 + 2];
        float cx  = coef[b * 3 + 0],  cy  = coef[b * 3 + 1],  cz  = coef[b * 3 + 2];
        float mx  = maxl[b * 3 + 0],  my  = maxl[b * 3 + 1],  mz  = maxl[b * 3 + 2];

        float fx_full = fmaxf(fminf((px - f0x) * cx, mx), 0.0f);
        float fy_full = fmaxf(fminf((py - f0y) * cy, my), 0.0f);
        float fz_full = fmaxf(fminf((pz - f0z) * cz, mz), 0.0f);

        float bx = floorf(fx_full);
        float by = floorf(fy_full);
        float bz = floorf(fz_full);
        float fx = fx_full - bx;
        float fy = fy_full - by;
        float fz = fz_full - bz;

        int ix = (int)bx, iy = (int)by, iz = (int)bz;

        const float* g = grid + (size_t)b * D * DD
                              + (size_t)ix * DD
                              + (size_t)iy * D
                              + (size_t)iz;

        // 8 gathers issued back-to-back (all independent)
        float c000 = __ldg(g);
        float c001 = __ldg(g + 1);
        float c010 = __ldg(g + D);
        float c011 = __ldg(g + D + 1);
        float c100 = __ldg(g + DD);
        float c101 = __ldg(g + DD + 1);
        float c110 = __ldg(g + DD + D);
        float c111 = __ldg(g + DD + D + 1);

        float wx0 = 1.0f - fx, wx1 = fx;
        float wy0 = 1.0f - fy, wy1 = fy;
        float wz0 = 1.0f - fz, wz1 = fz;

        // trilinear value (lerp chain: z, then y, then x)
        float a00 = fmaf(fz, c001 - c000, c000);
        float a01 = fmaf(fz, c011 - c010, c010);
        float a10 = fmaf(fz, c101 - c100, c100);
        float a11 = fmaf(fz, c111 - c110, c110);
        float b0  = fmaf(fy, a01 - a00, a00);
        float b1  = fmaf(fy, a11 - a10, a10);
        float d   = fmaf(fx, b1 - b0, b0);

        // finite-difference normals
        float nz = ((c001-c000) * wy0 + (c011-c010) * wy1) * wx0
                 + ((c101-c100) * wy0 + (c111-c110) * wy1) * wx1;
        float ny = ((c010-c000) * wz0 + (c011-c001) * wz1) * wx0
                 + ((c110-c100) * wz0 + (c111-c101) * wz1) * wx1;
        float nx = ((c100-c000) * wz0 + (c101-c001) * wz1) * wy0
                 + ((c110-c010) * wz0 + (c111-c011) * wz1) * wy1;

        // 1/max(sqrt(s), EPS) == min(rsqrt(s), 1/EPS) for s >= 0
        float s2  = nx * nx + ny * ny + nz * nz;
        float inv = fminf(rsqrtf(s2), 1.0f / EPS);

        dss[t] = d;
        nss[3 * (size_t)t + 0] = nx * inv;
        nss[3 * (size_t)t + 1] = ny * inv;
        nss[3 * (size_t)t + 2] = nz * inv;

        my_loss = -fminf(d, 0.0f);
    }

    // block reduction of loss, one atomic per block
    __shared__ float warp_sums[TPB / 32];
    int lane = threadIdx.x & 31;
    int warp = threadIdx.x >> 5;

    #pragma unroll
    for (int off = 16; off > 0; off >>= 1)
        my_loss += __shfl_down_sync(0xFFFFFFFFu, my_loss, off);
    if (lane == 0) warp_sums[warp] = my_loss;
    __syncthreads();

    if (warp == 0) {
        float s = (lane < (TPB >> 5)) ? warp_sums[lane] : 0.0f;
        #pragma unroll
        for (int off = 4; off > 0; off >>= 1)
            s += __shfl_down_sync(0xFFFFFFFFu, s, off);
        if (lane == 0)
            atomicAdd(loss, s);
    }
}

extern "C" void kernel_launch(void* const* d_in, const int* in_sizes, int n_in,
                              void* d_out, int out_size)
{
    const float* pss   = (const float*)d_in[0];
    const float* grid  = (const float*)d_in[1];
    const float* first = (const float*)d_in[2];
    const float* coef  = (const float*)d_in[3];
    const float* maxl  = (const float*)d_in[4];

    int B = in_sizes[2] / 3;
    int N = in_sizes[0] / (3 * B);
    long per_b = (long)in_sizes[1] / B;
    int D = 1;
    while ((long)(D + 1) * (D + 1) * (D + 1) <= per_b) D++;

    int total = B * N;

    float* dss  = (float*)d_out;
    float* nss  = dss + (size_t)total;
    float* loss = dss + (size_t)4 * total;

    // zero the loss accumulator (d_out is poisoned) — capturable async memset
    cudaMemsetAsync(loss, 0, sizeof(float));

    dim3 gridDims((N + TPB - 1) / TPB, B);
    sdf_trilinear_kernel<<<gridDims, TPB>>>(pss, grid, first, coef, maxl,
                                            dss, nss, loss, N, D);
}